// round 16
// baseline (speedup 1.0000x reference)
#include <cuda_runtime.h>
#include <cuda_bf16.h>
#include <cuda_fp16.h>
#include <cstdint>

// ============================================================================
// CustomLSTM: B=32, T=2048, I=512, H=512 (4H=2048)
// Phase 1: gx = x@Wi^T + bi + bh  -- bf16x3 HMMA, 128x128 tiles, SMEM-staged
//          transposed epilogue -> gx[t][g][b]. Init folded into block (0,0).
// Phase 2: persistent scan, 128 CTAs x 4 hidden units, fp16x2 HMMA.
//          Per-warp producer-set waits; DIRECT b16 h publish by gate threads;
//          named-bar tail (gate warps only) + release publish; double-buffered
//          partials so warps 4-7 run ahead. (R14 base.)
// NOTE: harness PTX target is compute_103 (no 'a') -> tcgen05 unavailable.
// ============================================================================

#define TT 2048
#define BB 32
#define II 512
#define HH 512
#define GG 2048

#define NCTA2 128

// ---------------- device scratch ----------------
__device__ float g_gx[(size_t)TT * GG * BB];     // [t][g][b]  512 MB
__device__ uint2 g_hf[2][BB * 128];              // ping x [b][cta] fp16 h (32KB)
__device__ int   g_flags[NCTA2 * 32];            // one flag per 128B line

__device__ __forceinline__ float sigf(float x) { return 1.0f / (1.0f + __expf(-x)); }
__device__ __forceinline__ float tanh_fast(float x) {
    float r;
    asm("tanh.approx.f32 %0, %1;" : "=f"(r) : "f"(x));
    return r;
}
__device__ __forceinline__ int ldflag_acq(const int* p) {
    int v;
    asm volatile("ld.acquire.gpu.global.b32 %0, [%1];" : "=r"(v) : "l"(p) : "memory");
    return v;
}
__device__ __forceinline__ void stflag_rel(int* p, int v) {
    asm volatile("st.release.gpu.global.b32 [%0], %1;" :: "l"(p), "r"(v) : "memory");
}

// ---- bf16 split (phase 1) ----
__device__ __forceinline__ void split_pair(float f0, float f1, uint32_t& hi2, uint32_t& lo2) {
    uint32_t h;
    asm("cvt.rn.bf16x2.f32 %0, %1, %2;" : "=r"(h) : "f"(f1), "f"(f0));
    float h0 = __uint_as_float(h << 16);
    float h1 = __uint_as_float(h & 0xFFFF0000u);
    asm("cvt.rn.bf16x2.f32 %0, %1, %2;" : "=r"(lo2) : "f"(f1 - h1), "f"(f0 - h0));
    hi2 = h;
}

// ---- fp16 split (scan Wh) ----
__device__ __forceinline__ void split_pair_f16(float f0, float f1, uint32_t& hi2, uint32_t& lo2) {
    uint32_t h;
    asm("cvt.rn.f16x2.f32 %0, %1, %2;" : "=r"(h) : "f"(f1), "f"(f0));
    __half2 hh = *reinterpret_cast<__half2*>(&h);
    float h0 = __low2float(hh), h1 = __high2float(hh);
    asm("cvt.rn.f16x2.f32 %0, %1, %2;" : "=r"(lo2) : "f"(f1 - h1), "f"(f0 - h0));
    hi2 = h;
}

__device__ __forceinline__ void mma_bf16(float* d, const uint32_t* a, const uint32_t* b) {
    asm volatile(
        "mma.sync.aligned.m16n8k16.row.col.f32.bf16.bf16.f32 "
        "{%0,%1,%2,%3}, {%4,%5,%6,%7}, {%8,%9}, {%0,%1,%2,%3};"
        : "+f"(d[0]), "+f"(d[1]), "+f"(d[2]), "+f"(d[3])
        : "r"(a[0]), "r"(a[1]), "r"(a[2]), "r"(a[3]), "r"(b[0]), "r"(b[1]));
}
__device__ __forceinline__ void mma_f16(float* d, const uint32_t* a, const uint32_t* b) {
    asm volatile(
        "mma.sync.aligned.m16n8k16.row.col.f32.f16.f16.f32 "
        "{%0,%1,%2,%3}, {%4,%5,%6,%7}, {%8,%9}, {%0,%1,%2,%3};"
        : "+f"(d[0]), "+f"(d[1]), "+f"(d[2]), "+f"(d[3])
        : "r"(a[0]), "r"(a[1]), "r"(a[2]), "r"(a[3]), "r"(b[0]), "r"(b[1]));
}

// ============================================================================
// Phase 1: bf16x3 HMMA GEMM; SMEM-staged transposed epilogue; init fold
// ============================================================================
#define P1_ROWB 80
#define P1_OPB  (128 * P1_ROWB)
#define P1_BUFB (4 * P1_OPB)
#define P1_SMEM (2 * P1_BUFB + 512)
#define EPI_STRIDE 36

__global__ __launch_bounds__(256, 2) void gemm_gx_tc(
    const float* __restrict__ x, const float* __restrict__ Wi,
    const float* __restrict__ bi, const float* __restrict__ bh)
{
    extern __shared__ char sm[];
    float* bias_sm = reinterpret_cast<float*>(sm + 2 * P1_BUFB);

    const int tid = threadIdx.x;
    const int wid = tid >> 5;
    const int lane = tid & 31;
    const int g = lane >> 2;
    const int t4 = lane & 3;
    const int wm = wid >> 2;
    const int wn = wid & 3;

    const int gn0 = blockIdx.x * 128;
    const int gm0 = blockIdx.y * 128;

    // ---- folded init (block 0,0): zero h ping 0 (fp16) and padded flags ----
    if (blockIdx.x == 0 && blockIdx.y == 0) {
#pragma unroll
        for (int it = 0; it < 16; ++it) {
            int i = tid + it * 256;
            g_hf[0][i] = make_uint2(0u, 0u);
        }
#pragma unroll
        for (int it = 0; it < 16; ++it)
            g_flags[tid + it * 256] = 0;
    }

    if (tid < 128) bias_sm[tid] = bi[gn0 + tid] + bh[gn0 + tid];

    const float* asrc[4];
    const float* bsrc[4];
    uint32_t adst[4], bdst[4];
#pragma unroll
    for (int it = 0; it < 4; ++it) {
        int aidx = tid + it * 256;
        int row = aidx >> 3, q = aidx & 7;
        int m = gm0 + row;
        asrc[it] = x + ((size_t)(m & 31) * TT + (m >> 5)) * II + q * 4;
        adst[it] = row * P1_ROWB + q * 8;
        bsrc[it] = Wi + (size_t)(gn0 + row) * II + q * 4;
        bdst[it] = row * P1_ROWB + q * 8;
    }

    float acc[4][4][4];
#pragma unroll
    for (int a = 0; a < 4; ++a)
#pragma unroll
        for (int b = 0; b < 4; ++b)
#pragma unroll
            for (int c = 0; c < 4; ++c) acc[a][b][c] = 0.0f;

    float4 v[8];
#pragma unroll
    for (int it = 0; it < 4; ++it) {
        v[it]     = *reinterpret_cast<const float4*>(asrc[it]);
        v[4 + it] = *reinterpret_cast<const float4*>(bsrc[it]);
    }

    for (int kt = 0; kt < 16; ++kt) {
        char* buf = sm + (kt & 1) * P1_BUFB;
#pragma unroll
        for (int it = 0; it < 8; ++it) {
            float4 w = v[it];
            uint32_t h01, l01, h23, l23;
            split_pair(w.x, w.y, h01, l01);
            split_pair(w.z, w.w, h23, l23);
            char* dhi = buf + ((it < 4) ? adst[it] : (2 * P1_OPB + bdst[it - 4]));
            *reinterpret_cast<uint2*>(dhi) = make_uint2(h01, h23);
            *reinterpret_cast<uint2*>(dhi + P1_OPB) = make_uint2(l01, l23);
        }
        __syncthreads();

        if (kt < 15) {
            int ko = (kt + 1) * 32;
#pragma unroll
            for (int it = 0; it < 4; ++it) {
                v[it]     = *reinterpret_cast<const float4*>(asrc[it] + ko);
                v[4 + it] = *reinterpret_cast<const float4*>(bsrc[it] + ko);
            }
        }

        const char* Ah = buf;
        const char* Al = buf + P1_OPB;
        const char* Bh = buf + 2 * P1_OPB;
        const char* Bl = buf + 3 * P1_OPB;

#pragma unroll
        for (int ks = 0; ks < 2; ++ks) {
            const int kb = ks * 32 + 4 * t4;
            uint32_t bhf[4][2], blf[4][2];
#pragma unroll
            for (int nt = 0; nt < 4; ++nt) {
                int n = wn * 32 + nt * 8 + g;
                const char* ph = Bh + n * P1_ROWB + kb;
                const char* pl = Bl + n * P1_ROWB + kb;
                bhf[nt][0] = *reinterpret_cast<const uint32_t*>(ph);
                bhf[nt][1] = *reinterpret_cast<const uint32_t*>(ph + 16);
                blf[nt][0] = *reinterpret_cast<const uint32_t*>(pl);
                blf[nt][1] = *reinterpret_cast<const uint32_t*>(pl + 16);
            }
#pragma unroll
            for (int mt = 0; mt < 4; ++mt) {
                int r = wm * 64 + mt * 16 + g;
                const char* ph = Ah + r * P1_ROWB + kb;
                const char* pl = Al + r * P1_ROWB + kb;
                uint32_t ahf[4], alf[4];
                ahf[0] = *reinterpret_cast<const uint32_t*>(ph);
                ahf[1] = *reinterpret_cast<const uint32_t*>(ph + 8 * P1_ROWB);
                ahf[2] = *reinterpret_cast<const uint32_t*>(ph + 16);
                ahf[3] = *reinterpret_cast<const uint32_t*>(ph + 8 * P1_ROWB + 16);
                alf[0] = *reinterpret_cast<const uint32_t*>(pl);
                alf[1] = *reinterpret_cast<const uint32_t*>(pl + 8 * P1_ROWB);
                alf[2] = *reinterpret_cast<const uint32_t*>(pl + 16);
                alf[3] = *reinterpret_cast<const uint32_t*>(pl + 8 * P1_ROWB + 16);
#pragma unroll
                for (int nt = 0; nt < 4; ++nt) {
                    mma_bf16(acc[mt][nt], ahf, bhf[nt]);
                    mma_bf16(acc[mt][nt], ahf, blf[nt]);
                    mma_bf16(acc[mt][nt], alf, bhf[nt]);
                }
            }
        }
        __syncthreads();
    }

    // ---- epilogue: stage [tloc][n][b] in SMEM, then coalesced STG ----
    float* stage = reinterpret_cast<float*>(sm);
#pragma unroll
    for (int mt = 0; mt < 4; ++mt) {
        int lm0 = wm * 64 + mt * 16 + g;
        int lm1 = lm0 + 8;
        int tl0 = lm0 >> 5, bb0 = lm0 & 31;
        int tl1 = lm1 >> 5, bb1 = lm1 & 31;
#pragma unroll
        for (int nt = 0; nt < 4; ++nt) {
            int nl = wn * 32 + nt * 8 + 2 * t4;
            float bv0 = bias_sm[nl], bv1 = bias_sm[nl + 1];
            stage[(tl0 * 128 + nl) * EPI_STRIDE + bb0]       = acc[mt][nt][0] + bv0;
            stage[(tl0 * 128 + nl + 1) * EPI_STRIDE + bb0]   = acc[mt][nt][1] + bv1;
            stage[(tl1 * 128 + nl) * EPI_STRIDE + bb1]       = acc[mt][nt][2] + bv0;
            stage[(tl1 * 128 + nl + 1) * EPI_STRIDE + bb1]   = acc[mt][nt][3] + bv1;
        }
    }
    __syncthreads();

    const size_t tbase = (size_t)(gm0 >> 5);
#pragma unroll
    for (int it = 0; it < 16; ++it) {
        int i = tid + it * 256;
        int row = i >> 3;
        int q = i & 7;
        int tloc = row >> 7, n = row & 127;
        float4 val = *reinterpret_cast<const float4*>(&stage[row * EPI_STRIDE + q * 4]);
        float* dst = g_gx + ((tbase + tloc) * GG + gn0 + n) * 32 + q * 4;
        *reinterpret_cast<float4*>(dst) = val;
    }
}

// ============================================================================
// Phase 2: persistent scan; direct-store publish, named-bar tail,
// double-buffered partials.
// ============================================================================
#define HW_SLAB 4608                          // per-warp: 32 b * 144B (fp16 h)
#define OFF_PART (8 * HW_SLAB)                // 36864
#define PART_SLABW (16 * 36)                  // 576 floats per warp slab
#define PARTBUF (8 * PART_SLABW * 4)          // 18432 bytes per buffer
#define SCAN_SMEM (OFF_PART + 2 * PARTBUF + 64)    // ~73.8 KB

__global__ __launch_bounds__(256, 1) void lstm_scan_tc(
    const float* __restrict__ Wh,
    float* __restrict__ y, float* __restrict__ hfin, float* __restrict__ cfin)
{
    extern __shared__ char sm[];
    const int tid = threadIdx.x;
    const int wid = tid >> 5;
    const int lane = tid & 31;
    const int g = lane >> 2;
    const int t4 = lane & 3;
    const int J0 = blockIdx.x * 4;
    const int kb = wid * 64;

    // ---- preload Wh A-fragments (fp16 hi/lo) into registers, once ----
    uint32_t ahf[4][4], alf[4][4];
    {
        const int grow0 = (g >> 2) * 512 + J0 + (g & 3);
        const int grow1 = grow0 + 1024;
#pragma unroll
        for (int ks = 0; ks < 4; ++ks) {
            int k0 = kb + ks * 16 + 2 * t4;
            float2 w00 = *reinterpret_cast<const float2*>(&Wh[(size_t)grow0 * HH + k0]);
            float2 w10 = *reinterpret_cast<const float2*>(&Wh[(size_t)grow1 * HH + k0]);
            float2 w01 = *reinterpret_cast<const float2*>(&Wh[(size_t)grow0 * HH + k0 + 8]);
            float2 w11 = *reinterpret_cast<const float2*>(&Wh[(size_t)grow1 * HH + k0 + 8]);
            split_pair_f16(w00.x, w00.y, ahf[ks][0], alf[ks][0]);
            split_pair_f16(w10.x, w10.y, ahf[ks][1], alf[ks][1]);
            split_pair_f16(w01.x, w01.y, ahf[ks][2], alf[ks][2]);
            split_pair_f16(w11.x, w11.y, ahf[ks][3], alf[ks][3]);
        }
    }

    char* wslab = sm + wid * HW_SLAB;
    const int jj = tid >> 5;                 // valid for tid<128 (0..3)
    const int b = tid & 31;

    // per-warp producer flag: warp w consumes h from CTAs [16w, 16w+16)
    const int* my_flag = &g_flags[(wid * 16 + (lane & 15)) * 32];

    float c_reg = 0.0f, h_last = 0.0f;

    for (int t = 0; t < TT; ++t) {
        const int p = t & 1;

        // gx prefetch (coalesced; in flight during the wait)
        float gx0 = 0.f, gx1 = 0.f, gx2 = 0.f, gx3 = 0.f;
        if (tid < 128) {
            const float* gxp = g_gx + ((size_t)t * GG + J0 + jj) * 32 + b;
            gx0 = gxp[0];
            gx1 = gxp[512 * 32];
            gx2 = gxp[1024 * 32];
            gx3 = gxp[1536 * 32];
        }

        // ---- per-warp wait: only this warp's 16 producer CTAs ----
        if (t > 0) {
            int f;
            do {
                f = ldflag_acq(my_flag);
            } while (!__all_sync(0xFFFFFFFFu, f >= t));
        }

        // ---- per-warp h slice copy (fp16, L2 .cg): k-chunk [kb,kb+64) ----
        const uint4* __restrict__ src = reinterpret_cast<const uint4*>(&g_hf[p][0]);
#pragma unroll
        for (int it = 0; it < 8; ++it) {
            int idx = lane + it * 32;          // 0..255
            int bb = idx >> 3, j = idx & 7;
            uint4 val = __ldcg(&src[bb * 64 + wid * 8 + j]);
            *reinterpret_cast<uint4*>(wslab + bb * 144 + j * 16) = val;
        }
        __syncwarp();

        // ---- MMA: 16 gate rows x 32 batches over warp k-chunk, fp16x2 ----
        float acc[4][4];
#pragma unroll
        for (int nt = 0; nt < 4; ++nt)
#pragma unroll
            for (int c = 0; c < 4; ++c) acc[nt][c] = 0.0f;

#pragma unroll
        for (int ks = 0; ks < 4; ++ks) {
            uint32_t bf[4][2];
#pragma unroll
            for (int nt = 0; nt < 4; ++nt) {
                const char* ph = wslab + (nt * 8 + g) * 144 + (ks * 8 + t4) * 4;
                bf[nt][0] = *reinterpret_cast<const uint32_t*>(ph);
                bf[nt][1] = *reinterpret_cast<const uint32_t*>(ph + 16);
            }
#pragma unroll
            for (int nt = 0; nt < 4; ++nt) {
                mma_f16(acc[nt], ahf[ks], bf[nt]);
                mma_f16(acc[nt], alf[ks], bf[nt]);
            }
        }

        // ---- partials to double-buffered SMEM slab ----
        {
            float* slab = reinterpret_cast<float*>(sm + OFF_PART + p * PARTBUF)
                          + wid * PART_SLABW;
#pragma unroll
            for (int nt = 0; nt < 4; ++nt) {
                int n = nt * 8 + 2 * t4;
                *reinterpret_cast<float2*>(&slab[g * 36 + n]) =
                    make_float2(acc[nt][0], acc[nt][1]);
                *reinterpret_cast<float2*>(&slab[(g + 8) * 36 + n]) =
                    make_float2(acc[nt][2], acc[nt][3]);
            }
        }
        __syncthreads();    // bar#1: partials(t) ready; warps 4-7 loop onward

        // ---- gate warps only (tid<128): reduce + gates + direct publish ----
        if (tid < 128) {
            const float* pbase =
                reinterpret_cast<const float*>(sm + OFF_PART + p * PARTBUF);
            float gate[4] = {gx0, gx1, gx2, gx3};
#pragma unroll
            for (int q = 0; q < 4; ++q) {
                const int m = q * 4 + jj;
#pragma unroll
                for (int w = 0; w < 8; ++w)
                    gate[q] += pbase[w * PART_SLABW + m * 36 + b];
            }
            float cn = sigf(gate[1]) * c_reg + sigf(gate[0]) * tanh_fast(gate[2]);
            float hn = sigf(gate[3]) * tanh_fast(cn);
            c_reg = cn;
            h_last = hn;

            // direct b16 store into g_hf[p^1][b*128+cta].half[jj]
            __half* hb = reinterpret_cast<__half*>(&g_hf[p ^ 1][0]);
            hb[(size_t)(b * 128 + blockIdx.x) * 4 + jj] = __float2half_rn(hn);

            asm volatile("bar.sync 2, 128;" ::: "memory");   // gate warps only
            if (tid == 0 && t < TT - 1) {
                stflag_rel(&g_flags[blockIdx.x * 32], t + 1);   // release publish
            }
            // y after publish (off the critical path)
            y[((size_t)b * TT + t) * HH + J0 + jj] = hn;
        }
    }

    if (tid < 128) {
        hfin[(size_t)b * HH + J0 + jj] = h_last;
        cfin[(size_t)b * HH + J0 + jj] = c_reg;
    }
}

// ============================================================================
// launch (2 kernels; init folded into gemm)
// ============================================================================
extern "C" void kernel_launch(void* const* d_in, const int* in_sizes, int n_in,
                              void* d_out, int out_size) {
    const float* x  = (const float*)d_in[0];
    const float* Wi = (const float*)d_in[1];
    const float* bi = (const float*)d_in[2];
    const float* Wh = (const float*)d_in[3];
    const float* bh = (const float*)d_in[4];

    float* y    = (float*)d_out;
    float* hfin = y + (size_t)BB * TT * HH;
    float* cfin = hfin + (size_t)BB * HH;

    cudaFuncSetAttribute(gemm_gx_tc,
                         cudaFuncAttributeMaxDynamicSharedMemorySize, P1_SMEM);
    cudaFuncSetAttribute(lstm_scan_tc,
                         cudaFuncAttributeMaxDynamicSharedMemorySize, SCAN_SMEM);

    gemm_gx_tc<<<dim3(16, 512), 256, P1_SMEM>>>(x, Wi, bi, bh);
    lstm_scan_tc<<<NCTA2, 256, SCAN_SMEM>>>(Wh, y, hfin, cfin);
}

// round 17
// speedup vs baseline: 1.1090x; 1.1090x over previous
#include <cuda_runtime.h>
#include <cuda_bf16.h>
#include <cuda_fp16.h>
#include <cstdint>

// ============================================================================
// CustomLSTM: B=32, T=2048, I=512, H=512 (4H=2048)
// Phase 1: gx = x@Wi^T + bi + bh  -- fp16x2 HMMA (x as fp16, Wi as fp16
//          hi+lo), 128x128 tiles, SMEM-staged transposed epilogue ->
//          gx[t][g][b]. Init folded into block (0,0).
// Phase 2: persistent scan (R14, proven): 128 CTAs x 4 hidden units, fp16x2
//          HMMA, per-warp producer-set waits, warp-0 packed publish with
//          st.release.gpu.
// NOTE: harness PTX target is compute_103 (no 'a') -> tcgen05 unavailable.
// ============================================================================

#define TT 2048
#define BB 32
#define II 512
#define HH 512
#define GG 2048

#define NCTA2 128

// ---------------- device scratch ----------------
__device__ float g_gx[(size_t)TT * GG * BB];     // [t][g][b]  512 MB
__device__ uint2 g_hf[2][BB * 128];              // ping x [b][cta] fp16 h (32KB)
__device__ int   g_flags[NCTA2 * 32];            // one flag per 128B line

__device__ __forceinline__ float sigf(float x) { return 1.0f / (1.0f + __expf(-x)); }
__device__ __forceinline__ float tanh_fast(float x) {
    float r;
    asm("tanh.approx.f32 %0, %1;" : "=f"(r) : "f"(x));
    return r;
}
__device__ __forceinline__ int ldflag_acq(const int* p) {
    int v;
    asm volatile("ld.acquire.gpu.global.b32 %0, [%1];" : "=r"(v) : "l"(p) : "memory");
    return v;
}
__device__ __forceinline__ void stflag_rel(int* p, int v) {
    asm volatile("st.release.gpu.global.b32 [%0], %1;" :: "l"(p), "r"(v) : "memory");
}

// ---- fp16 helpers ----
__device__ __forceinline__ uint32_t pack_f16(float f0, float f1) {
    uint32_t h;
    asm("cvt.rn.f16x2.f32 %0, %1, %2;" : "=r"(h) : "f"(f1), "f"(f0));
    return h;
}
__device__ __forceinline__ void split_pair_f16(float f0, float f1, uint32_t& hi2, uint32_t& lo2) {
    uint32_t h;
    asm("cvt.rn.f16x2.f32 %0, %1, %2;" : "=r"(h) : "f"(f1), "f"(f0));
    __half2 hh = *reinterpret_cast<__half2*>(&h);
    float h0 = __low2float(hh), h1 = __high2float(hh);
    asm("cvt.rn.f16x2.f32 %0, %1, %2;" : "=r"(lo2) : "f"(f1 - h1), "f"(f0 - h0));
    hi2 = h;
}

__device__ __forceinline__ void mma_f16(float* d, const uint32_t* a, const uint32_t* b) {
    asm volatile(
        "mma.sync.aligned.m16n8k16.row.col.f32.f16.f16.f32 "
        "{%0,%1,%2,%3}, {%4,%5,%6,%7}, {%8,%9}, {%0,%1,%2,%3};"
        : "+f"(d[0]), "+f"(d[1]), "+f"(d[2]), "+f"(d[3])
        : "r"(a[0]), "r"(a[1]), "r"(a[2]), "r"(a[3]), "r"(b[0]), "r"(b[1]));
}

// ============================================================================
// Phase 1: fp16x2 HMMA GEMM; SMEM-staged transposed epilogue; init fold
//   operands in SMEM: A = x (fp16), Bh/Bl = Wi hi/lo (fp16)
// ============================================================================
#define P1_ROWB 80
#define P1_OPB  (128 * P1_ROWB)              // 10240 per operand array
#define P1_BUFB (3 * P1_OPB)                 // 30720 per stage buffer
#define P1_BIAS 73728                        // bias after epilogue stage area
#define P1_SMEM (73728 + 576)
#define EPI_STRIDE 36

__global__ __launch_bounds__(256, 2) void gemm_gx_tc(
    const float* __restrict__ x, const float* __restrict__ Wi,
    const float* __restrict__ bi, const float* __restrict__ bh)
{
    extern __shared__ char sm[];
    float* bias_sm = reinterpret_cast<float*>(sm + P1_BIAS);

    const int tid = threadIdx.x;
    const int wid = tid >> 5;
    const int lane = tid & 31;
    const int g = lane >> 2;
    const int t4 = lane & 3;
    const int wm = wid >> 2;
    const int wn = wid & 3;

    const int gn0 = blockIdx.x * 128;
    const int gm0 = blockIdx.y * 128;

    // ---- folded init (block 0,0): zero h ping 0 (fp16) and padded flags ----
    if (blockIdx.x == 0 && blockIdx.y == 0) {
#pragma unroll
        for (int it = 0; it < 16; ++it) {
            int i = tid + it * 256;
            g_hf[0][i] = make_uint2(0u, 0u);
        }
#pragma unroll
        for (int it = 0; it < 16; ++it)
            g_flags[tid + it * 256] = 0;
    }

    if (tid < 128) bias_sm[tid] = bi[gn0 + tid] + bh[gn0 + tid];

    const float* asrc[4];
    const float* bsrc[4];
    uint32_t adst[4], bdst[4];
#pragma unroll
    for (int it = 0; it < 4; ++it) {
        int aidx = tid + it * 256;
        int row = aidx >> 3, q = aidx & 7;
        int m = gm0 + row;
        asrc[it] = x + ((size_t)(m & 31) * TT + (m >> 5)) * II + q * 4;
        adst[it] = row * P1_ROWB + q * 8;
        bsrc[it] = Wi + (size_t)(gn0 + row) * II + q * 4;
        bdst[it] = row * P1_ROWB + q * 8;
    }

    float acc[4][4][4];
#pragma unroll
    for (int a = 0; a < 4; ++a)
#pragma unroll
        for (int b = 0; b < 4; ++b)
#pragma unroll
            for (int c = 0; c < 4; ++c) acc[a][b][c] = 0.0f;

    float4 v[8];
#pragma unroll
    for (int it = 0; it < 4; ++it) {
        v[it]     = *reinterpret_cast<const float4*>(asrc[it]);
        v[4 + it] = *reinterpret_cast<const float4*>(bsrc[it]);
    }

    for (int kt = 0; kt < 16; ++kt) {
        char* buf = sm + (kt & 1) * P1_BUFB;
        // stage: A (x) as plain fp16; B (Wi) as fp16 hi/lo
#pragma unroll
        for (int it = 0; it < 4; ++it) {
            float4 w = v[it];
            uint32_t p01 = pack_f16(w.x, w.y);
            uint32_t p23 = pack_f16(w.z, w.w);
            *reinterpret_cast<uint2*>(buf + adst[it]) = make_uint2(p01, p23);
        }
#pragma unroll
        for (int it = 0; it < 4; ++it) {
            float4 w = v[4 + it];
            uint32_t h01, l01, h23, l23;
            split_pair_f16(w.x, w.y, h01, l01);
            split_pair_f16(w.z, w.w, h23, l23);
            char* dhi = buf + P1_OPB + bdst[it];
            *reinterpret_cast<uint2*>(dhi) = make_uint2(h01, h23);
            *reinterpret_cast<uint2*>(dhi + P1_OPB) = make_uint2(l01, l23);
        }
        __syncthreads();

        if (kt < 15) {
            int ko = (kt + 1) * 32;
#pragma unroll
            for (int it = 0; it < 4; ++it) {
                v[it]     = *reinterpret_cast<const float4*>(asrc[it] + ko);
                v[4 + it] = *reinterpret_cast<const float4*>(bsrc[it] + ko);
            }
        }

        const char* Aa = buf;
        const char* Bh = buf + P1_OPB;
        const char* Bl = buf + 2 * P1_OPB;

#pragma unroll
        for (int ks = 0; ks < 2; ++ks) {
            const int kb = ks * 32 + 4 * t4;
            uint32_t bhf[4][2], blf[4][2];
#pragma unroll
            for (int nt = 0; nt < 4; ++nt) {
                int n = wn * 32 + nt * 8 + g;
                const char* ph = Bh + n * P1_ROWB + kb;
                const char* pl = Bl + n * P1_ROWB + kb;
                bhf[nt][0] = *reinterpret_cast<const uint32_t*>(ph);
                bhf[nt][1] = *reinterpret_cast<const uint32_t*>(ph + 16);
                blf[nt][0] = *reinterpret_cast<const uint32_t*>(pl);
                blf[nt][1] = *reinterpret_cast<const uint32_t*>(pl + 16);
            }
#pragma unroll
            for (int mt = 0; mt < 4; ++mt) {
                int r = wm * 64 + mt * 16 + g;
                const char* pa = Aa + r * P1_ROWB + kb;
                uint32_t af[4];
                af[0] = *reinterpret_cast<const uint32_t*>(pa);
                af[1] = *reinterpret_cast<const uint32_t*>(pa + 8 * P1_ROWB);
                af[2] = *reinterpret_cast<const uint32_t*>(pa + 16);
                af[3] = *reinterpret_cast<const uint32_t*>(pa + 8 * P1_ROWB + 16);
#pragma unroll
                for (int nt = 0; nt < 4; ++nt) {
                    mma_f16(acc[mt][nt], af, bhf[nt]);
                    mma_f16(acc[mt][nt], af, blf[nt]);
                }
            }
        }
        __syncthreads();
    }

    // ---- epilogue: stage [tloc][n][b] in SMEM, then coalesced STG ----
    float* stage = reinterpret_cast<float*>(sm);
#pragma unroll
    for (int mt = 0; mt < 4; ++mt) {
        int lm0 = wm * 64 + mt * 16 + g;
        int lm1 = lm0 + 8;
        int tl0 = lm0 >> 5, bb0 = lm0 & 31;
        int tl1 = lm1 >> 5, bb1 = lm1 & 31;
#pragma unroll
        for (int nt = 0; nt < 4; ++nt) {
            int nl = wn * 32 + nt * 8 + 2 * t4;
            float bv0 = bias_sm[nl], bv1 = bias_sm[nl + 1];
            stage[(tl0 * 128 + nl) * EPI_STRIDE + bb0]       = acc[mt][nt][0] + bv0;
            stage[(tl0 * 128 + nl + 1) * EPI_STRIDE + bb0]   = acc[mt][nt][1] + bv1;
            stage[(tl1 * 128 + nl) * EPI_STRIDE + bb1]       = acc[mt][nt][2] + bv0;
            stage[(tl1 * 128 + nl + 1) * EPI_STRIDE + bb1]   = acc[mt][nt][3] + bv1;
        }
    }
    __syncthreads();

    const size_t tbase = (size_t)(gm0 >> 5);
#pragma unroll
    for (int it = 0; it < 16; ++it) {
        int i = tid + it * 256;
        int row = i >> 3;
        int q = i & 7;
        int tloc = row >> 7, n = row & 127;
        float4 val = *reinterpret_cast<const float4*>(&stage[row * EPI_STRIDE + q * 4]);
        float* dst = g_gx + ((tbase + tloc) * GG + gn0 + n) * 32 + q * 4;
        *reinterpret_cast<float4*>(dst) = val;
    }
}

// ============================================================================
// Phase 2: persistent scan (R14, unchanged)
// ============================================================================
#define HW_SLAB 4608                          // per-warp: 32 b * 144B (fp16 h)
#define OFF_PART (8 * HW_SLAB)                // 36864
#define PART_SLABW (16 * 36)                  // 576 floats per warp slab
#define OFF_HROW (OFF_PART + 8 * PART_SLABW * 4)   // 55296
#define SCAN_SMEM (OFF_HROW + 32 * 5 * 4 + 64)     // 56000

__global__ __launch_bounds__(256, 1) void lstm_scan_tc(
    const float* __restrict__ Wh,
    float* __restrict__ y, float* __restrict__ hfin, float* __restrict__ cfin)
{
    extern __shared__ char sm[];
    const int tid = threadIdx.x;
    const int wid = tid >> 5;
    const int lane = tid & 31;
    const int g = lane >> 2;
    const int t4 = lane & 3;
    const int J0 = blockIdx.x * 4;
    const int kb = wid * 64;

    // ---- preload Wh A-fragments (fp16 hi/lo) into registers, once ----
    uint32_t ahf[4][4], alf[4][4];
    {
        const int grow0 = (g >> 2) * 512 + J0 + (g & 3);
        const int grow1 = grow0 + 1024;
#pragma unroll
        for (int ks = 0; ks < 4; ++ks) {
            int k0 = kb + ks * 16 + 2 * t4;
            float2 w00 = *reinterpret_cast<const float2*>(&Wh[(size_t)grow0 * HH + k0]);
            float2 w10 = *reinterpret_cast<const float2*>(&Wh[(size_t)grow1 * HH + k0]);
            float2 w01 = *reinterpret_cast<const float2*>(&Wh[(size_t)grow0 * HH + k0 + 8]);
            float2 w11 = *reinterpret_cast<const float2*>(&Wh[(size_t)grow1 * HH + k0 + 8]);
            split_pair_f16(w00.x, w00.y, ahf[ks][0], alf[ks][0]);
            split_pair_f16(w10.x, w10.y, ahf[ks][1], alf[ks][1]);
            split_pair_f16(w01.x, w01.y, ahf[ks][2], alf[ks][2]);
            split_pair_f16(w11.x, w11.y, ahf[ks][3], alf[ks][3]);
        }
    }

    char* wslab = sm + wid * HW_SLAB;
    const int jj = tid >> 5;                 // valid for tid<128 (0..3)
    const int b = tid & 31;

    // per-warp producer flag: warp w consumes h from CTAs [16w, 16w+16)
    const int* my_flag = &g_flags[(wid * 16 + (lane & 15)) * 32];

    float c_reg = 0.0f, h_last = 0.0f;

    for (int t = 0; t < TT; ++t) {
        const int p = t & 1;

        // gx prefetch (coalesced; in flight during the wait)
        float gx0 = 0.f, gx1 = 0.f, gx2 = 0.f, gx3 = 0.f;
        if (tid < 128) {
            const float* gxp = g_gx + ((size_t)t * GG + J0 + jj) * 32 + b;
            gx0 = gxp[0];
            gx1 = gxp[512 * 32];
            gx2 = gxp[1024 * 32];
            gx3 = gxp[1536 * 32];
        }

        // ---- per-warp wait: only this warp's 16 producer CTAs ----
        if (t > 0) {
            int f;
            do {
                f = ldflag_acq(my_flag);
            } while (!__all_sync(0xFFFFFFFFu, f >= t));
        }

        // ---- per-warp h slice copy (fp16, L2 .cg): k-chunk [kb,kb+64) ----
        const uint4* __restrict__ src = reinterpret_cast<const uint4*>(&g_hf[p][0]);
#pragma unroll
        for (int it = 0; it < 8; ++it) {
            int idx = lane + it * 32;          // 0..255
            int bb = idx >> 3, j = idx & 7;
            uint4 val = __ldcg(&src[bb * 64 + wid * 8 + j]);
            *reinterpret_cast<uint4*>(wslab + bb * 144 + j * 16) = val;
        }
        __syncwarp();

        // ---- MMA: 16 gate rows x 32 batches over warp k-chunk, fp16x2 ----
        float acc[4][4];
#pragma unroll
        for (int nt = 0; nt < 4; ++nt)
#pragma unroll
            for (int c = 0; c < 4; ++c) acc[nt][c] = 0.0f;

#pragma unroll
        for (int ks = 0; ks < 4; ++ks) {
            uint32_t bf[4][2];
#pragma unroll
            for (int nt = 0; nt < 4; ++nt) {
                const char* ph = wslab + (nt * 8 + g) * 144 + (ks * 8 + t4) * 4;
                bf[nt][0] = *reinterpret_cast<const uint32_t*>(ph);
                bf[nt][1] = *reinterpret_cast<const uint32_t*>(ph + 16);
            }
#pragma unroll
            for (int nt = 0; nt < 4; ++nt) {
                mma_f16(acc[nt], ahf[ks], bf[nt]);
                mma_f16(acc[nt], alf[ks], bf[nt]);
            }
        }

        // ---- partials to SMEM ----
        {
            float* slab = reinterpret_cast<float*>(sm + OFF_PART) + wid * PART_SLABW;
#pragma unroll
            for (int nt = 0; nt < 4; ++nt) {
                int n = nt * 8 + 2 * t4;
                *reinterpret_cast<float2*>(&slab[g * 36 + n]) =
                    make_float2(acc[nt][0], acc[nt][1]);
                *reinterpret_cast<float2*>(&slab[(g + 8) * 36 + n]) =
                    make_float2(acc[nt][2], acc[nt][3]);
            }
        }
        __syncthreads();

        // ---- fused reduce + gate math: thread (jj, b), tid<128 ----
        if (tid < 128) {
            const float* pbase = reinterpret_cast<const float*>(sm + OFF_PART);
            float gate[4] = {gx0, gx1, gx2, gx3};
#pragma unroll
            for (int q = 0; q < 4; ++q) {
                const int m = q * 4 + jj;
#pragma unroll
                for (int w = 0; w < 8; ++w)
                    gate[q] += pbase[w * PART_SLABW + m * 36 + b];
            }
            float cn = sigf(gate[1]) * c_reg + sigf(gate[0]) * tanh_fast(gate[2]);
            float hn = sigf(gate[3]) * tanh_fast(cn);
            c_reg = cn;
            h_last = hn;
            reinterpret_cast<float*>(sm + OFF_HROW)[b * 5 + jj] = hn;
        }
        __syncthreads();

        // ---- writer warp 0: h -> global fp16; release-publish; THEN y ----
        if (tid < 32) {
            const float* hr = reinterpret_cast<const float*>(sm + OFF_HROW) + tid * 5;
            float h0 = hr[0], h1 = hr[1], h2 = hr[2], h3 = hr[3];
            uint32_t p01 = pack_f16(h0, h1);
            uint32_t p23 = pack_f16(h2, h3);
            g_hf[p ^ 1][tid * 128 + blockIdx.x] = make_uint2(p01, p23);
            __syncwarp();
            if (tid == 0 && t < TT - 1) {
                stflag_rel(&g_flags[blockIdx.x * 32], t + 1);   // release publish
            }
            // y after publish (off the critical path)
            float* yp = y + ((size_t)tid * TT + t) * HH + J0;
            *reinterpret_cast<float4*>(yp) = make_float4(h0, h1, h2, h3);
        }
    }

    if (tid < 128) {
        hfin[(size_t)b * HH + J0 + jj] = h_last;
        cfin[(size_t)b * HH + J0 + jj] = c_reg;
    }
}

// ============================================================================
// launch (2 kernels; init folded into gemm)
// ============================================================================
extern "C" void kernel_launch(void* const* d_in, const int* in_sizes, int n_in,
                              void* d_out, int out_size) {
    const float* x  = (const float*)d_in[0];
    const float* Wi = (const float*)d_in[1];
    const float* bi = (const float*)d_in[2];
    const float* Wh = (const float*)d_in[3];
    const float* bh = (const float*)d_in[4];

    float* y    = (float*)d_out;
    float* hfin = y + (size_t)BB * TT * HH;
    float* cfin = hfin + (size_t)BB * HH;

    cudaFuncSetAttribute(gemm_gx_tc,
                         cudaFuncAttributeMaxDynamicSharedMemorySize, P1_SMEM);
    cudaFuncSetAttribute(lstm_scan_tc,
                         cudaFuncAttributeMaxDynamicSharedMemorySize, SCAN_SMEM);

    gemm_gx_tc<<<dim3(16, 512), 256, P1_SMEM>>>(x, Wi, bi, bh);
    lstm_scan_tc<<<NCTA2, 256, SCAN_SMEM>>>(Wh, y, hfin, cfin);
}